// round 7
// baseline (speedup 1.0000x reference)
#include <cuda_runtime.h>
#include <math.h>
#include <stdint.h>

#define BB 4
#define LL 2048
#define DD 1024
#define HH 16
#define HD 64

// Q prescale: 1/sqrt(64) * log2(e), so softmax can use exp2 directly.
#define QSCALE 0.1803368801111204f

// Scratch (device globals)
__device__ float    g_qkv[(size_t)BB * LL * 3 * DD];   // tf32 bits, hd-permuted, Q pre-scaled
__device__ float    g_att[(size_t)BB * LL * DD];       // tf32 bits, D-permuted
__device__ uint32_t g_xt  [(size_t)BB * LL * DD];      // x tf32, K-permuted
__device__ uint32_t g_wq  [(size_t)3 * DD * DD];       // Wqkv tf32, K-permuted + row-permuted
__device__ uint32_t g_wo  [(size_t)DD * DD];           // Wout tf32, K-permuted
__device__ float    g_bq  [3 * DD];                    // qkv bias, permuted

__device__ __forceinline__ uint32_t f2tf32(float x) {
    uint32_t r;
    asm("cvt.rna.tf32.f32 %0, %1;" : "=r"(r) : "f"(x));
    return r;
}
__device__ __host__ __forceinline__ int pos8(int i) {
    int g = i & 7;
    return (i & ~7) | ((g < 4) ? (g << 1) : (((g - 4) << 1) | 1));
}

__device__ __forceinline__ void cp_async16(uint32_t smem_addr, const void* gptr) {
    asm volatile("cp.async.cg.shared.global [%0], [%1], 16;\n"
                 :: "r"(smem_addr), "l"(gptr));
}
__device__ __forceinline__ void cp_commit() {
    asm volatile("cp.async.commit_group;\n" ::: "memory");
}
template <int N>
__device__ __forceinline__ void cp_wait() {
    asm volatile("cp.async.wait_group %0;\n" :: "n"(N) : "memory");
}

// m16n8k8 tf32 mma. A frag: a0=(r,qc) a1=(r+8,qc) a2=(r,qc+4) a3=(r+8,qc+4)
// B frag: b0=(k=qc,n=qr) b1=(k=qc+4,n=qr). C: c0=(r,2qc) c1=(r,2qc+1) c2/c3 = +8 rows.
__device__ __forceinline__ void mma_tf32(float* d, const uint32_t* a,
                                         uint32_t b0, uint32_t b1) {
    asm volatile(
        "mma.sync.aligned.m16n8k8.row.col.f32.tf32.tf32.f32 "
        "{%0,%1,%2,%3}, {%4,%5,%6,%7}, {%8,%9}, {%0,%1,%2,%3};\n"
        : "+f"(d[0]), "+f"(d[1]), "+f"(d[2]), "+f"(d[3])
        : "r"(a[0]), "r"(a[1]), "r"(a[2]), "r"(a[3]), "r"(b0), "r"(b1));
}

// ---------------------------------------------------------------------------
// Prepass: fp32 -> tf32 bits, K permuted within 8-groups; optional row perm.
// ---------------------------------------------------------------------------
template <int PERM_ROWS>
__global__ void perm_tf32_kernel(const float* __restrict__ in,
                                 uint32_t* __restrict__ out, int rows, int cols) {
    int gid = blockIdx.x * blockDim.x + threadIdx.x;
    const int gpr = cols >> 3;
    if (gid >= rows * gpr) return;
    const int r = gid / gpr;
    const int gk = gid - r * gpr;
    const float4 v0 = *(const float4*)(in + (size_t)r * cols + gk * 8);
    const float4 v1 = *(const float4*)(in + (size_t)r * cols + gk * 8 + 4);
    const int rp = PERM_ROWS ? pos8(r) : r;
    uint32_t* o = out + (size_t)rp * cols + gk * 8;
    o[0] = f2tf32(v0.x); o[2] = f2tf32(v0.y); o[4] = f2tf32(v0.z); o[6] = f2tf32(v0.w);
    o[1] = f2tf32(v1.x); o[3] = f2tf32(v1.y); o[5] = f2tf32(v1.z); o[7] = f2tf32(v1.w);
}

__global__ void perm_bias_kernel(const float* __restrict__ in,
                                 float* __restrict__ out, int n) {
    int i = blockIdx.x * blockDim.x + threadIdx.x;
    if (i < n) out[pos8(i)] = in[i];
}

// ---------------------------------------------------------------------------
// tf32 GEMM (mma.sync), C = A @ W^T + bias. K pre-permuted on both operands.
// Block 128x128, kTile 32, 8 warps (4x2), warp 32x64. 3-stage cp.async,
// one __syncthreads per kTile. Padding-free XOR-swizzled smem rows
// (32 words/row, w ^= (row&3)<<3): fragment LDS.64 conflict-free per phase.
// __launch_bounds__(256,2) -> 2 CTAs/SM = 16 warps = 4/SMSP.
// MODE 0: fp32 out. MODE 1: tf32 bits out, cols<DD scaled by QSCALE.
// ---------------------------------------------------------------------------
#define GBUF (128 * 32)                     // words per operand per stage
#define SMEM_GEMM (3 * GBUF * 2 * 4)        // 96 KB

__device__ __forceinline__ uint32_t swz32(uint32_t row, uint32_t w) {
    return row * 32 + (w ^ ((row & 3) << 3));
}

template <int MODE>
__global__ __launch_bounds__(256, 2) void gemm_tf32(
    const uint32_t* __restrict__ A, const uint32_t* __restrict__ W,
    const float* __restrict__ bias, float* __restrict__ C,
    int M, int N, int K)
{
    extern __shared__ uint32_t gsm[];   // As[3][GBUF] | Ws[3][GBUF]

    const int tid = threadIdx.x;
    const int lane = tid & 31;
    const int ww = tid >> 5;
    const int wr = ww >> 1;          // 0..3 (32-row band)
    const int wc = ww & 1;           // 0..1 (64-col band)
    const int qr = lane >> 2;        // 0..7
    const int qc = lane & 3;         // 0..3
    const int bm = blockIdx.y * 128;
    const int bn = blockIdx.x * 128;

    float acc[2][8][4];
#pragma unroll
    for (int i = 0; i < 2; i++)
#pragma unroll
        for (int j = 0; j < 8; j++)
#pragma unroll
            for (int c = 0; c < 4; c++) acc[i][j][c] = 0.0f;

    const uint32_t sm_base = (uint32_t)__cvta_generic_to_shared(gsm);
    const int nkt = K / 32;

    auto stage = [&](int kt_idx, int s) {
#pragma unroll
        for (int i = 0; i < 4; i++) {          // A: 1024 chunks of 16B
            const int q = i * 256 + tid;
            const int r = q >> 3, c = q & 7;
            cp_async16(sm_base + (uint32_t)((s * GBUF + swz32(r, c * 4)) * 4),
                       A + (size_t)(bm + r) * K + kt_idx * 32 + c * 4);
        }
#pragma unroll
        for (int i = 0; i < 4; i++) {          // B: 1024 chunks
            const int q = i * 256 + tid;
            const int r = q >> 3, c = q & 7;
            cp_async16(sm_base + (uint32_t)((3 * GBUF + s * GBUF + swz32(r, c * 4)) * 4),
                       W + (size_t)(bn + r) * K + kt_idx * 32 + c * 4);
        }
        cp_commit();
    };

    stage(0, 0);
    stage(1, 1);

    int s = 0;
    for (int kt = 0; kt < nkt; kt++) {
        if (kt + 1 < nkt) cp_wait<1>();
        else              cp_wait<0>();
        __syncthreads();
        if (kt + 2 < nkt) {
            int s2 = s + 2; if (s2 >= 3) s2 -= 3;
            stage(kt + 2, s2);
        }

        const uint32_t* As = gsm + s * GBUF;
        const uint32_t* Ws = gsm + 3 * GBUF + s * GBUF;

#pragma unroll
        for (int ks = 0; ks < 32; ks += 8) {
            uint32_t aa[2][4], bb[8][2];
#pragma unroll
            for (int mi = 0; mi < 2; mi++) {
                const int m = wr * 32 + mi * 16 + qr;
                const uint2 u0 = *(const uint2*)&As[swz32(m, ks + 2 * qc)];
                const uint2 u1 = *(const uint2*)&As[swz32(m + 8, ks + 2 * qc)];
                aa[mi][0] = u0.x; aa[mi][1] = u1.x;
                aa[mi][2] = u0.y; aa[mi][3] = u1.y;
            }
#pragma unroll
            for (int ni = 0; ni < 8; ni++) {
                const int n = wc * 64 + ni * 8 + qr;
                const uint2 v = *(const uint2*)&Ws[swz32(n, ks + 2 * qc)];
                bb[ni][0] = v.x; bb[ni][1] = v.y;
            }
#pragma unroll
            for (int mi = 0; mi < 2; mi++)
#pragma unroll
                for (int ni = 0; ni < 8; ni++)
                    mma_tf32(acc[mi][ni], aa[mi], bb[ni][0], bb[ni][1]);
        }
        s++; if (s == 3) s = 0;
    }

#pragma unroll
    for (int mi = 0; mi < 2; mi++) {
        const int row = bm + wr * 32 + mi * 16 + qr;
#pragma unroll
        for (int ni = 0; ni < 8; ni++) {
            const int col = bn + wc * 64 + ni * 8 + qc * 2;
            const float b0 = bias[col], b1 = bias[col + 1];
            float* d = acc[mi][ni];
            float v00 = d[0] + b0, v01 = d[1] + b1;
            float v10 = d[2] + b0, v11 = d[3] + b1;
            if (MODE == 1) {
                const float sc = (col < DD) ? QSCALE : 1.0f;
                v00 = __uint_as_float(f2tf32(v00 * sc));
                v01 = __uint_as_float(f2tf32(v01 * sc));
                v10 = __uint_as_float(f2tf32(v10 * sc));
                v11 = __uint_as_float(f2tf32(v11 * sc));
            }
            *(float2*)(C + (size_t)row * N + col)       = make_float2(v00, v01);
            *(float2*)(C + (size_t)(row + 8) * N + col) = make_float2(v10, v11);
        }
    }
}

// ---------------------------------------------------------------------------
// Causal flash attention (unchanged from R6, passing): tf32 mma, 4 warps,
// q-tile 128, P register-resident, V rows pos8-inverse-permuted, exp2 softmax.
// ---------------------------------------------------------------------------
#define KST 72
#define VST 72
#define K_WORDS (64 * KST)
#define V_WORDS (64 * VST)
#define OFF_K0 0
#define OFF_V0 (2 * K_WORDS)
#define SMEM_ATTN ((2 * K_WORDS + 2 * V_WORDS) * 4)

__global__ __launch_bounds__(128) void attn_tf32_kernel(
    const float* __restrict__ qkvf, float* __restrict__ out)
{
    extern __shared__ uint32_t sm[];
    const uint32_t* qkv = (const uint32_t*)qkvf;

    const int qt = gridDim.x - 1 - blockIdx.x;
    const int h  = blockIdx.y;
    const int b  = blockIdx.z;

    const int tid = threadIdx.x;
    const int lane = tid & 31;
    const int w = tid >> 5;
    const int qr = lane >> 2;
    const int qc = lane & 3;

    const size_t rs = 3 * DD;
    const uint32_t sm_base = (uint32_t)__cvta_generic_to_shared(sm);

    uint32_t qa[2][8][4];
    const uint32_t* qb = qkv + ((size_t)(b * LL + qt * 128 + w * 32)) * rs + h * HD;
#pragma unroll
    for (int mi = 0; mi < 2; mi++)
#pragma unroll
        for (int ks = 0; ks < 8; ks++) {
            const size_t r0 = (size_t)(mi * 16 + qr) * rs;
            const uint2 u0 = *(const uint2*)(qb + r0 + ks * 8 + 2 * qc);
            const uint2 u1 = *(const uint2*)(qb + r0 + 8 * rs + ks * 8 + 2 * qc);
            qa[mi][ks][0] = u0.x; qa[mi][ks][1] = u1.x;
            qa[mi][ks][2] = u0.y; qa[mi][ks][3] = u1.y;
        }

    float o[2][8][4];
    float m[2][2], l[2][2];
#pragma unroll
    for (int mi = 0; mi < 2; mi++) {
        m[mi][0] = m[mi][1] = -INFINITY;
        l[mi][0] = l[mi][1] = 0.0f;
#pragma unroll
        for (int j = 0; j < 8; j++)
#pragma unroll
            for (int c = 0; c < 4; c++) o[mi][j][c] = 0.0f;
    }

    const int jmax = 2 * qt + 1;

    auto stage = [&](int jt, int s) {
        const uint32_t* kg = qkv + ((size_t)(b * LL + jt * 64)) * rs + DD + h * HD;
        const uint32_t* vg = kg + DD;
#pragma unroll
        for (int i = 0; i < 8; i++) {
            const int q = i * 128 + tid;
            const int r = q >> 4, c = q & 15;
            cp_async16(sm_base + (uint32_t)((OFF_K0 + s * K_WORDS + r * KST + c * 4) * 4),
                       kg + (size_t)r * rs + c * 4);
        }
#pragma unroll
        for (int i = 0; i < 8; i++) {
            const int q = i * 128 + tid;
            const int r = q >> 4, c = q & 15;
            const int g = r & 7;
            const int pr = (r & ~7) | ((g & 1) ? ((g >> 1) + 4) : (g >> 1));
            cp_async16(sm_base + (uint32_t)((OFF_V0 + s * V_WORDS + pr * VST + c * 4) * 4),
                       vg + (size_t)r * rs + c * 4);
        }
        cp_commit();
    };

    stage(0, 0);

    for (int jt = 0; jt <= jmax; jt++) {
        const int s = jt & 1;
        __syncthreads();
        if (jt + 1 <= jmax) { stage(jt + 1, s ^ 1); cp_wait<1>(); }
        else                { cp_wait<0>(); }
        __syncthreads();

        const uint32_t* Ks = sm + OFF_K0 + s * K_WORDS;
        const uint32_t* Vs = sm + OFF_V0 + s * V_WORDS;

        const int wrow_min = qt * 128 + w * 32;
        const bool tile_dead = (jt * 64) > (wrow_min + 31);

        if (!tile_dead) {
            float sreg[2][8][4];
#pragma unroll
            for (int mi = 0; mi < 2; mi++)
#pragma unroll
                for (int j = 0; j < 8; j++)
#pragma unroll
                    for (int c = 0; c < 4; c++) sreg[mi][j][c] = 0.0f;

#pragma unroll
            for (int ks = 0; ks < 8; ks++) {
#pragma unroll
                for (int j = 0; j < 8; j++) {
                    const uint2 kk = *(const uint2*)&Ks[(j * 8 + qr) * KST + ks * 8 + 2 * qc];
                    mma_tf32(sreg[0][j], qa[0][ks], kk.x, kk.y);
                    mma_tf32(sreg[1][j], qa[1][ks], kk.x, kk.y);
                }
            }

            if ((jt + 1) * 64 - 1 > wrow_min) {
#pragma unroll
                for (int mi = 0; mi < 2; mi++) {
                    const int r0 = wrow_min + mi * 16 + qr;
#pragma unroll
                    for (int j = 0; j < 8; j++) {
                        const int c0 = jt * 64 + j * 8 + qc * 2;
                        if (c0     > r0)     sreg[mi][j][0] = -INFINITY;
                        if (c0 + 1 > r0)     sreg[mi][j][1] = -INFINITY;
                        if (c0     > r0 + 8) sreg[mi][j][2] = -INFINITY;
                        if (c0 + 1 > r0 + 8) sreg[mi][j][3] = -INFINITY;
                    }
                }
            }

#pragma unroll
            for (int mi = 0; mi < 2; mi++) {
                float mt0 = -INFINITY, mt1 = -INFINITY;
#pragma unroll
                for (int j = 0; j < 8; j++) {
                    mt0 = fmaxf(mt0, fmaxf(sreg[mi][j][0], sreg[mi][j][1]));
                    mt1 = fmaxf(mt1, fmaxf(sreg[mi][j][2], sreg[mi][j][3]));
                }
#pragma unroll
                for (int off = 1; off <= 2; off <<= 1) {
                    mt0 = fmaxf(mt0, __shfl_xor_sync(0xffffffffu, mt0, off));
                    mt1 = fmaxf(mt1, __shfl_xor_sync(0xffffffffu, mt1, off));
                }
                const float mn0 = fmaxf(m[mi][0], mt0);
                const float mn1 = fmaxf(m[mi][1], mt1);
                const float al0 = exp2f(m[mi][0] - mn0);
                const float al1 = exp2f(m[mi][1] - mn1);
                m[mi][0] = mn0; m[mi][1] = mn1;
                float rs0 = 0.0f, rs1 = 0.0f;
#pragma unroll
                for (int j = 0; j < 8; j++) {
                    sreg[mi][j][0] = exp2f(sreg[mi][j][0] - mn0);
                    sreg[mi][j][1] = exp2f(sreg[mi][j][1] - mn0);
                    sreg[mi][j][2] = exp2f(sreg[mi][j][2] - mn1);
                    sreg[mi][j][3] = exp2f(sreg[mi][j][3] - mn1);
                    rs0 += sreg[mi][j][0] + sreg[mi][j][1];
                    rs1 += sreg[mi][j][2] + sreg[mi][j][3];
                }
#pragma unroll
                for (int off = 1; off <= 2; off <<= 1) {
                    rs0 += __shfl_xor_sync(0xffffffffu, rs0, off);
                    rs1 += __shfl_xor_sync(0xffffffffu, rs1, off);
                }
                l[mi][0] = l[mi][0] * al0 + rs0;
                l[mi][1] = l[mi][1] * al1 + rs1;
#pragma unroll
                for (int j = 0; j < 8; j++) {
                    o[mi][j][0] *= al0; o[mi][j][1] *= al0;
                    o[mi][j][2] *= al1; o[mi][j][3] *= al1;
                }
            }

#pragma unroll
            for (int ks = 0; ks < 8; ks++) {
                uint32_t pa0[4], pa1[4];
                pa0[0] = f2tf32(sreg[0][ks][0]); pa0[1] = f2tf32(sreg[0][ks][2]);
                pa0[2] = f2tf32(sreg[0][ks][1]); pa0[3] = f2tf32(sreg[0][ks][3]);
                pa1[0] = f2tf32(sreg[1][ks][0]); pa1[1] = f2tf32(sreg[1][ks][2]);
                pa1[2] = f2tf32(sreg[1][ks][1]); pa1[3] = f2tf32(sreg[1][ks][3]);
#pragma unroll
                for (int j = 0; j < 8; j++) {
                    const uint32_t b0 = Vs[(ks * 8 + qc) * VST + j * 8 + qr];
                    const uint32_t b1 = Vs[(ks * 8 + 4 + qc) * VST + j * 8 + qr];
                    mma_tf32(o[0][j], pa0, b0, b1);
                    mma_tf32(o[1][j], pa1, b0, b1);
                }
            }
        }
    }

    float* ob = out + ((size_t)(b * LL + qt * 128 + w * 32)) * DD + h * HD;
#pragma unroll
    for (int mi = 0; mi < 2; mi++) {
        const float inv0 = 1.0f / l[mi][0];
        const float inv1 = 1.0f / l[mi][1];
        const size_t r0 = (size_t)(mi * 16 + qr) * DD;
#pragma unroll
        for (int j = 0; j < 8; j++) {
            const int col = j * 8 + qc * 2;
            uint2 v0 = make_uint2(f2tf32(o[mi][j][0] * inv0), f2tf32(o[mi][j][1] * inv0));
            uint2 v1 = make_uint2(f2tf32(o[mi][j][2] * inv1), f2tf32(o[mi][j][3] * inv1));
            *(uint2*)(ob + r0 + col)          = v0;
            *(uint2*)(ob + r0 + 8 * DD + col) = v1;
        }
    }
}

// ---------------------------------------------------------------------------
extern "C" void kernel_launch(void* const* d_in, const int* in_sizes, int n_in,
                              void* d_out, int out_size)
{
    const float* x    = (const float*)d_in[0];
    const float* Wqkv = (const float*)d_in[1];
    const float* bqkv = (const float*)d_in[2];
    const float* Wout = (const float*)d_in[3];
    const float* bout = (const float*)d_in[4];
    float* outp = (float*)d_out;

    float *qkv = nullptr, *att = nullptr, *bq = nullptr;
    uint32_t *xt = nullptr, *wq = nullptr, *wo = nullptr;
    cudaGetSymbolAddress((void**)&qkv, g_qkv);
    cudaGetSymbolAddress((void**)&att, g_att);
    cudaGetSymbolAddress((void**)&xt, g_xt);
    cudaGetSymbolAddress((void**)&wq, g_wq);
    cudaGetSymbolAddress((void**)&wo, g_wo);
    cudaGetSymbolAddress((void**)&bq, g_bq);

    static bool attr_set = false;
    if (!attr_set) {
        cudaFuncSetAttribute(attn_tf32_kernel,
                             cudaFuncAttributeMaxDynamicSharedMemorySize, SMEM_ATTN);
        cudaFuncSetAttribute(gemm_tf32<0>,
                             cudaFuncAttributeMaxDynamicSharedMemorySize, SMEM_GEMM);
        cudaFuncSetAttribute(gemm_tf32<1>,
                             cudaFuncAttributeMaxDynamicSharedMemorySize, SMEM_GEMM);
        attr_set = true;
    }

    const int M = BB * LL;  // 8192

    // prepass: tf32 + K-permutation (+ row perm for Wqkv), bias perm
    {
        int ng = (M * DD) / 8;
        perm_tf32_kernel<0><<<(ng + 255) / 256, 256>>>(x, xt, M, DD);
        ng = (3 * DD * DD) / 8;
        perm_tf32_kernel<1><<<(ng + 255) / 256, 256>>>(Wqkv, wq, 3 * DD, DD);
        ng = (DD * DD) / 8;
        perm_tf32_kernel<0><<<(ng + 255) / 256, 256>>>(Wout, wo, DD, DD);
        perm_bias_kernel<<<12, 256>>>(bqkv, bq, 3 * DD);
    }

    // 1) QKV projection (tf32 bits out, Q pre-scaled by QSCALE, hd-permuted)
    {
        dim3 grid((3 * DD) / 128, M / 128);
        gemm_tf32<1><<<grid, 256, SMEM_GEMM>>>(xt, wq, bq, qkv, M, 3 * DD, DD);
    }

    // 2) causal attention
    {
        dim3 grid(LL / 128, HH, BB);
        attn_tf32_kernel<<<grid, 128, SMEM_ATTN>>>(qkv, att);
    }

    // 3) output projection (fp32 out)
    {
        dim3 grid(DD / 128, M / 128);
        gemm_tf32<0><<<grid, 256, SMEM_GEMM>>>((const uint32_t*)att, wo, bout, outp, M, DD, DD);
    }
}

// round 8
// speedup vs baseline: 1.8154x; 1.8154x over previous
#include <cuda_runtime.h>
#include <math.h>
#include <stdint.h>

#define BB 4
#define LL 2048
#define DD 1024
#define HH 16
#define HD 64

// Q prescale: 1/sqrt(64) * log2(e) -> softmax in exp2 domain.
#define QSCALE 0.1803368801111204f

// Scratch (device globals). All fp16 payloads stored as packed uint32 words.
__device__ float    g_qkv[(size_t)BB * LL * 3 * DD];       // fp16 words [M][1536]
__device__ float    g_att[(size_t)BB * LL * DD];           // fp16 words [M][512]
__device__ uint32_t g_xt  [(size_t)BB * LL * DD];          // x fp16 words [M][512]
__device__ uint32_t g_wq  [(size_t)3 * DD * DD];           // Wqkv fp16 words [3072][512]
__device__ uint32_t g_wo  [(size_t)DD * DD];               // Wout fp16 words [1024][512]
__device__ uint32_t g_vt  [(size_t)BB * HH * HD * (LL/2)]; // V^T fp16 words [(b,h,hd)][1024]

// pos8 on word index within an 8-word (16-elem) group: i<4 -> 2i, else 2i-7.
__device__ __host__ __forceinline__ int pos8(int i) {
    return (i < 4) ? (i << 1) : ((i << 1) - 7);
}

__device__ __forceinline__ uint32_t pack_f16x2(float lo, float hi) {
    uint32_t r;
    asm("cvt.rn.f16x2.f32 %0, %1, %2;" : "=r"(r) : "f"(hi), "f"(lo));
    return r;
}

__device__ __forceinline__ void cp_async16(uint32_t smem_addr, const void* gptr) {
    asm volatile("cp.async.cg.shared.global [%0], [%1], 16;\n"
                 :: "r"(smem_addr), "l"(gptr));
}
__device__ __forceinline__ void cp_commit() {
    asm volatile("cp.async.commit_group;\n" ::: "memory");
}
template <int N>
__device__ __forceinline__ void cp_wait() {
    asm volatile("cp.async.wait_group %0;\n" :: "n"(N) : "memory");
}

// m16n8k16 f16 mma, f32 acc.
// A: a0=(qr, k2qc..+1) a1=(qr+8, same) a2=(qr, k2qc+8..+9) a3=(qr+8, same)
// B: b0=(k2qc..+1, n=qr) b1=(k2qc+8..+9, n=qr)
// C: c0=(qr,2qc) c1=(qr,2qc+1) c2,c3 = +8 rows.
__device__ __forceinline__ void mma_f16(float* d, const uint32_t* a,
                                        uint32_t b0, uint32_t b1) {
    asm volatile(
        "mma.sync.aligned.m16n8k16.row.col.f32.f16.f16.f32 "
        "{%0,%1,%2,%3}, {%4,%5,%6,%7}, {%8,%9}, {%0,%1,%2,%3};\n"
        : "+f"(d[0]), "+f"(d[1]), "+f"(d[2]), "+f"(d[3])
        : "r"(a[0]), "r"(a[1]), "r"(a[2]), "r"(a[3]), "r"(b0), "r"(b1));
}

// ---------------------------------------------------------------------------
// Prepass: fp32 -> fp16 words, word index pos8-permuted within 16-elem groups.
// One thread per 16 elements.
// ---------------------------------------------------------------------------
__global__ void perm_f16_kernel(const float* __restrict__ in,
                                uint32_t* __restrict__ out, int rows, int cols) {
    int gid = blockIdx.x * blockDim.x + threadIdx.x;
    const int gpr = cols >> 4;
    if (gid >= rows * gpr) return;
    const int r = gid / gpr;
    const int gk = gid - r * gpr;
    const float* ip = in + (size_t)r * cols + gk * 16;
    uint32_t* op = out + (size_t)r * (cols >> 1) + gk * 8;
    float e[16];
#pragma unroll
    for (int i = 0; i < 16; i += 4) {
        float4 v = *(const float4*)(ip + i);
        e[i] = v.x; e[i + 1] = v.y; e[i + 2] = v.z; e[i + 3] = v.w;
    }
#pragma unroll
    for (int i = 0; i < 8; i++)
        op[pos8(i)] = pack_f16x2(e[2 * i], e[2 * i + 1]);
}

// ---------------------------------------------------------------------------
// fp16 GEMM (mma.sync m16n8k16), C = A @ W^T + bias.
// A:[M][Kw] W:[N][Kw] fp16 words, k-words pos8-permuted (both operands).
// Block 128x128, kTile 16 words (32 elems), 4 warps (2x2), warp 64x64,
// 3-stage cp.async, stride-24 smem rows (fragment LDS.64 conflict-free).
// MODE 0: fp32 out + bias. MODE 1: fp16 words out, logical cols<DD scaled by
//         QSCALE, word-perm applied for cols<2DD (Q,K), V section linear.
// ---------------------------------------------------------------------------
#define GST 24
#define GBUF (128 * GST)
#define SMEM_GEMM (3 * GBUF * 2 * 4)    // 72 KB

template <int MODE>
__global__ __launch_bounds__(128) void gemm_f16(
    const uint32_t* __restrict__ A, const uint32_t* __restrict__ W,
    const float* __restrict__ bias, float* __restrict__ C,
    int M, int N, int Kw)
{
    extern __shared__ uint32_t gsm[];   // As[3][GBUF] | Ws[3][GBUF]

    const int tid = threadIdx.x;
    const int lane = tid & 31;
    const int ww = tid >> 5;
    const int wr = ww >> 1;
    const int wc = ww & 1;
    const int qr = lane >> 2;
    const int qc = lane & 3;
    const int bm = blockIdx.y * 128;
    const int bn = blockIdx.x * 128;

    float acc[4][8][4];
#pragma unroll
    for (int i = 0; i < 4; i++)
#pragma unroll
        for (int j = 0; j < 8; j++)
#pragma unroll
            for (int c = 0; c < 4; c++) acc[i][j][c] = 0.0f;

    const uint32_t sm_base = (uint32_t)__cvta_generic_to_shared(gsm);
    const int nkt = Kw / 16;

    auto stage = [&](int kt_idx, int s) {
#pragma unroll
        for (int i = 0; i < 8; i++) {       // 512 A chunks + 512 W chunks of 16B
            const int q = i * 128 + tid;
            const int r = (q & 511) >> 2;
            const int c = q & 3;
            if (q < 512) {
                cp_async16(sm_base + (uint32_t)((s * GBUF + r * GST + c * 4) * 4),
                           A + (size_t)(bm + r) * Kw + kt_idx * 16 + c * 4);
            } else {
                cp_async16(sm_base + (uint32_t)((3 * GBUF + s * GBUF + r * GST + c * 4) * 4),
                           W + (size_t)(bn + r) * Kw + kt_idx * 16 + c * 4);
            }
        }
        cp_commit();
    };

    stage(0, 0);
    stage(1, 1);

    int s = 0;
    for (int kt = 0; kt < nkt; kt++) {
        if (kt + 1 < nkt) cp_wait<1>();
        else              cp_wait<0>();
        __syncthreads();
        if (kt + 2 < nkt) {
            int s2 = s + 2; if (s2 >= 3) s2 -= 3;
            stage(kt + 2, s2);
        }

        const uint32_t* As = gsm + s * GBUF;
        const uint32_t* Ws = gsm + 3 * GBUF + s * GBUF;

#pragma unroll
        for (int ks = 0; ks < 16; ks += 8) {   // two k16 steps
            uint32_t aa[4][4], bb[8][2];
#pragma unroll
            for (int mi = 0; mi < 4; mi++) {
                const int m = wr * 64 + mi * 16 + qr;
                const uint2 u0 = *(const uint2*)&As[m * GST + ks + 2 * qc];
                const uint2 u1 = *(const uint2*)&As[(m + 8) * GST + ks + 2 * qc];
                aa[mi][0] = u0.x; aa[mi][1] = u1.x;
                aa[mi][2] = u0.y; aa[mi][3] = u1.y;
            }
#pragma unroll
            for (int ni = 0; ni < 8; ni++) {
                const int n = wc * 64 + ni * 8 + qr;
                const uint2 v = *(const uint2*)&Ws[n * GST + ks + 2 * qc];
                bb[ni][0] = v.x; bb[ni][1] = v.y;
            }
#pragma unroll
            for (int mi = 0; mi < 4; mi++)
#pragma unroll
                for (int ni = 0; ni < 8; ni++)
                    mma_f16(acc[mi][ni], aa[mi], bb[ni][0], bb[ni][1]);
        }
        s++; if (s == 3) s = 0;
    }

#pragma unroll
    for (int mi = 0; mi < 4; mi++) {
        const int row = bm + wr * 64 + mi * 16 + qr;
#pragma unroll
        for (int ni = 0; ni < 8; ni++) {
            const int col = bn + wc * 64 + ni * 8 + qc * 2;
            const float b0 = bias[col], b1 = bias[col + 1];
            float* d = acc[mi][ni];
            float v00 = d[0] + b0, v01 = d[1] + b1;
            float v10 = d[2] + b0, v11 = d[3] + b1;
            if (MODE == 1) {
                const float sc = (col < DD) ? QSCALE : 1.0f;
                v00 *= sc; v01 *= sc; v10 *= sc; v11 *= sc;
                const int w = col >> 1;
                const int wp = (col < 2 * DD) ? ((w & ~7) | pos8(w & 7)) : w;
                uint32_t* C32 = (uint32_t*)C;
                C32[(size_t)row * (N >> 1) + wp]       = pack_f16x2(v00, v01);
                C32[(size_t)(row + 8) * (N >> 1) + wp] = pack_f16x2(v10, v11);
            } else {
                *(float2*)(C + (size_t)row * N + col)       = make_float2(v00, v01);
                *(float2*)(C + (size_t)(row + 8) * N + col) = make_float2(v10, v11);
            }
        }
    }
}

// ---------------------------------------------------------------------------
// V transpose: g_qkv V section (fp16 words, [seq][hd-pairs], linear) ->
// g_vt [(b,h,hd)][seq-pairs], seq-word index pos8-permuted within 8-word groups.
// Grid (B*H, L/64), 128 threads; 64 seq x 64 hd block via smem.
// ---------------------------------------------------------------------------
__global__ __launch_bounds__(128) void transpose_v_kernel(
    const float* __restrict__ qkvf, uint32_t* __restrict__ vt)
{
    __shared__ uint32_t ts[64][33];
    const int bh = blockIdx.x;
    const int b = bh >> 4, h = bh & 15;
    const int sc = blockIdx.y;
    const int tid = threadIdx.x;

    const uint32_t* vg = (const uint32_t*)qkvf
        + ((size_t)(b * LL + sc * 64)) * 1536 + 1024 + h * 32;
#pragma unroll
    for (int i = 0; i < 16; i++) {
        const int q = i * 128 + tid;
        const int r = q >> 5, c = q & 31;
        ts[r][c] = vg[(size_t)r * 1536 + c];
    }
    __syncthreads();

#pragma unroll
    for (int i = 0; i < 16; i++) {
        const int q = i * 128 + tid;
        const int hd = q >> 5, sw = q & 31;
        const uint32_t w0 = ts[2 * sw][hd >> 1];
        const uint32_t w1 = ts[2 * sw + 1][hd >> 1];
        const uint32_t sh = (hd & 1) * 16;
        const uint32_t val = ((w0 >> sh) & 0xffffu) | (((w1 >> sh) & 0xffffu) << 16);
        const int swp = (sw & ~7) | pos8(sw & 7);
        vt[((size_t)(bh * 64 + hd)) * (LL / 2) + sc * 32 + swp] = val;
    }
}

// ---------------------------------------------------------------------------
// Causal flash attention, fp16 mma. Grid (L/128, H, B) qt reversed, 4 warps.
// K smem [seq][hd-words] stride 40; Vt smem [hd][seq-words] stride 40.
// Q fragments register-resident; P packed from registers (no P smem).
// Softmax exp2; Q pre-scaled by QSCALE in GEMM1 epilogue.
// ---------------------------------------------------------------------------
#define AST 40
#define TILE_WORDS (64 * AST)
#define OFF_K0 0
#define OFF_V0 (2 * TILE_WORDS)
#define SMEM_ATTN (4 * TILE_WORDS * 4)   // 40 KB

__global__ __launch_bounds__(128) void attn_f16_kernel(
    const float* __restrict__ qkvf, const uint32_t* __restrict__ vt,
    float* __restrict__ outf)
{
    extern __shared__ uint32_t sm[];
    const uint32_t* qkv = (const uint32_t*)qkvf;
    uint32_t* att = (uint32_t*)outf;

    const int qt = gridDim.x - 1 - blockIdx.x;
    const int h  = blockIdx.y;
    const int b  = blockIdx.z;

    const int tid = threadIdx.x;
    const int lane = tid & 31;
    const int wid = tid >> 5;
    const int qr = lane >> 2;
    const int qc = lane & 3;

    const uint32_t sm_base = (uint32_t)__cvta_generic_to_shared(sm);

    // Q fragments (fp16 words, pos8-permuted, pre-scaled)
    uint32_t qa[2][4][4];
    const uint32_t* qb = qkv + ((size_t)(b * LL + qt * 128 + wid * 32)) * 1536 + h * 32;
#pragma unroll
    for (int mi = 0; mi < 2; mi++)
#pragma unroll
        for (int ks = 0; ks < 4; ks++) {
            const size_t r0 = (size_t)(mi * 16 + qr) * 1536;
            const uint2 u0 = *(const uint2*)(qb + r0 + ks * 8 + 2 * qc);
            const uint2 u1 = *(const uint2*)(qb + r0 + 8 * 1536 + ks * 8 + 2 * qc);
            qa[mi][ks][0] = u0.x; qa[mi][ks][1] = u1.x;
            qa[mi][ks][2] = u0.y; qa[mi][ks][3] = u1.y;
        }

    float o[2][8][4];
    float m[2][2], l[2][2];
#pragma unroll
    for (int mi = 0; mi < 2; mi++) {
        m[mi][0] = m[mi][1] = -INFINITY;
        l[mi][0] = l[mi][1] = 0.0f;
#pragma unroll
        for (int j = 0; j < 8; j++)
#pragma unroll
            for (int c = 0; c < 4; c++) o[mi][j][c] = 0.0f;
    }

    const int jmax = 2 * qt + 1;
    const uint32_t* vtb = vt + ((size_t)((b * HH + h) * 64)) * (LL / 2);

    auto stage = [&](int jt, int s) {
        const uint32_t* kg = qkv + ((size_t)(b * LL + jt * 64)) * 1536 + 512 + h * 32;
#pragma unroll
        for (int i = 0; i < 4; i++) {       // K: 512 chunks of 16B
            const int q = i * 128 + tid;
            const int r = q >> 3, c = q & 7;
            cp_async16(sm_base + (uint32_t)((OFF_K0 + s * TILE_WORDS + r * AST + c * 4) * 4),
                       kg + (size_t)r * 1536 + c * 4);
        }
#pragma unroll
        for (int i = 0; i < 4; i++) {       // Vt: 512 chunks
            const int q = i * 128 + tid;
            const int r = q >> 3, c = q & 7;
            cp_async16(sm_base + (uint32_t)((OFF_V0 + s * TILE_WORDS + r * AST + c * 4) * 4),
                       vtb + (size_t)r * (LL / 2) + jt * 32 + c * 4);
        }
        cp_commit();
    };

    stage(0, 0);

    for (int jt = 0; jt <= jmax; jt++) {
        const int s = jt & 1;
        __syncthreads();
        if (jt + 1 <= jmax) { stage(jt + 1, s ^ 1); cp_wait<1>(); }
        else                { cp_wait<0>(); }
        __syncthreads();

        const uint32_t* Ks = sm + OFF_K0 + s * TILE_WORDS;
        const uint32_t* Vs = sm + OFF_V0 + s * TILE_WORDS;

        const int wrow_min = qt * 128 + wid * 32;
        const bool tile_dead = (jt * 64) > (wrow_min + 31);

        if (!tile_dead) {
            // S = Q K^T
            float sreg[2][8][4];
#pragma unroll
            for (int mi = 0; mi < 2; mi++)
#pragma unroll
                for (int j = 0; j < 8; j++)
#pragma unroll
                    for (int c = 0; c < 4; c++) sreg[mi][j][c] = 0.0f;

#pragma unroll
            for (int ks = 0; ks < 4; ks++) {
#pragma unroll
                for (int j = 0; j < 8; j++) {
                    const uint2 kk = *(const uint2*)&Ks[(j * 8 + qr) * AST + ks * 8 + 2 * qc];
                    mma_f16(sreg[0][j], qa[0][ks], kk.x, kk.y);
                    mma_f16(sreg[1][j], qa[1][ks], kk.x, kk.y);
                }
            }

            // causal mask
            if ((jt + 1) * 64 - 1 > wrow_min) {
#pragma unroll
                for (int mi = 0; mi < 2; mi++) {
                    const int r0 = wrow_min + mi * 16 + qr;
#pragma unroll
                    for (int j = 0; j < 8; j++) {
                        const int c0 = jt * 64 + j * 8 + qc * 2;
                        if (c0     > r0)     sreg[mi][j][0] = -INFINITY;
                        if (c0 + 1 > r0)     sreg[mi][j][1] = -INFINITY;
                        if (c0     > r0 + 8) sreg[mi][j][2] = -INFINITY;
                        if (c0 + 1 > r0 + 8) sreg[mi][j][3] = -INFINITY;
                    }
                }
            }

            // online softmax (base 2)
#pragma unroll
            for (int mi = 0; mi < 2; mi++) {
                float mt0 = -INFINITY, mt1 = -INFINITY;
#pragma unroll
                for (int j = 0; j < 8; j++) {
                    mt0 = fmaxf(mt0, fmaxf(sreg[mi][j][0], sreg[mi][j][1]));
                    mt1 = fmaxf(mt1, fmaxf(sreg[mi][j][2], sreg[mi][j][3]));
                }
#pragma unroll
                for (int off = 1; off <= 2; off <<= 1) {
                    mt0 = fmaxf(mt0, __shfl_xor_sync(0xffffffffu, mt0, off));
                    mt1 = fmaxf(mt1, __shfl_xor_sync(0xffffffffu, mt1, off));
                }
                const float mn0 = fmaxf(m[mi][0], mt0);
                const float mn1 = fmaxf(m[mi][1], mt1);
                const float al0 = exp2f(m[mi][0] - mn0);
                const float al1 = exp2f(m[mi][1] - mn1);
                m[mi][0] = mn0; m[mi][1] = mn1;
                float rs0 = 0.0f, rs1 = 0.0f;
#pragma unroll
                for (int j = 0; j < 8; j++) {
                    sreg[mi][j][0] = exp2f(sreg[mi][j][0] - mn0);
                    sreg[mi][j][1] = exp2f(sreg[mi][j][1] - mn0);
                    sreg[mi][j][2] = exp2f(sreg[mi][j][2] - mn1);
                    sreg[mi][j][3] = exp2f(sreg[mi][j][3] - mn1);
                    rs0 += sreg[mi][j][0] + sreg[mi][j][1];
                    rs1 += sreg[mi][j][2] + sreg[mi][j][3];
                }
#pragma unroll
                for (int off = 1; off <= 2; off <<= 1) {
                    rs0 += __shfl_xor_sync(0xffffffffu, rs0, off);
                    rs1 += __shfl_xor_sync(0xffffffffu, rs1, off);
                }
                l[mi][0] = l[mi][0] * al0 + rs0;
                l[mi][1] = l[mi][1] * al1 + rs1;
#pragma unroll
                for (int j = 0; j < 8; j++) {
                    o[mi][j][0] *= al0; o[mi][j][1] *= al0;
                    o[mi][j][2] *= al1; o[mi][j][3] *= al1;
                }
            }

            // O += P @ V^T : P packed from registers, Vt B-frags LDS.64
#pragma unroll
            for (int ks = 0; ks < 4; ks++) {
                uint32_t pa0[4], pa1[4];
                pa0[0] = pack_f16x2(sreg[0][2 * ks][0],     sreg[0][2 * ks][1]);
                pa0[1] = pack_f16x2(sreg[0][2 * ks][2],     sreg[0][2 * ks][3]);
                pa0[2] = pack_f16x2(sreg[0][2 * ks + 1][0], sreg[0][2 * ks + 1][1]);
                pa0[3] = pack_f16x2(sreg[0][2 * ks + 1][2], sreg[0][2 * ks + 1][3]);
                pa1[0] = pack_f16x2(sreg[1][2 * ks][0],     sreg[1][2 * ks][1]);
                pa1[1] = pack_f16x2(sreg[1][2 * ks][2],     sreg[1][2 * ks][3]);
                pa1[2] = pack_f16x2(sreg[1][2 * ks + 1][0], sreg[1][2 * ks + 1][1]);
                pa1[3] = pack_f16x2(sreg[1][2 * ks + 1][2], sreg[1][2 * ks + 1][3]);
#pragma unroll
                for (int j = 0; j < 8; j++) {
                    const uint2 vv = *(const uint2*)&Vs[(j * 8 + qr) * AST + ks * 8 + 2 * qc];
                    mma_f16(o[0][j], pa0, vv.x, vv.y);
                    mma_f16(o[1][j], pa1, vv.x, vv.y);
                }
            }
        }
    }

    // epilogue: fp16 words, word index pos8-permuted (GEMM0 layout)
    const int orow0 = b * LL + qt * 128 + wid * 32;
#pragma unroll
    for (int mi = 0; mi < 2; mi++) {
        const float inv0 = 1.0f / l[mi][0];
        const float inv1 = 1.0f / l[mi][1];
        const size_t r0 = (size_t)(orow0 + mi * 16 + qr) * 512;
#pragma unroll
        for (int j = 0; j < 8; j++) {
            const int wl = j * 4 + qc;
            const int wp = h * 32 + ((wl & ~7) | pos8(wl & 7));
            att[r0 + wp]             = pack_f16x2(o[mi][j][0] * inv0, o[mi][j][1] * inv0);
            att[r0 + 8 * 512 + wp]   = pack_f16x2(o[mi][j][2] * inv1, o[mi][j][3] * inv1);
        }
    }
}

// ---------------------------------------------------------------------------
extern "C" void kernel_launch(void* const* d_in, const int* in_sizes, int n_in,
                              void* d_out, int out_size)
{
    const float* x    = (const float*)d_in[0];
    const float* Wqkv = (const float*)d_in[1];
    const float* bqkv = (const float*)d_in[2];
    const float* Wout = (const float*)d_in[3];
    const float* bout = (const float*)d_in[4];
    float* outp = (float*)d_out;

    float *qkv = nullptr, *att = nullptr;
    uint32_t *xt = nullptr, *wq = nullptr, *wo = nullptr, *vt = nullptr;
    cudaGetSymbolAddress((void**)&qkv, g_qkv);
    cudaGetSymbolAddress((void**)&att, g_att);
    cudaGetSymbolAddress((void**)&xt, g_xt);
    cudaGetSymbolAddress((void**)&wq, g_wq);
    cudaGetSymbolAddress((void**)&wo, g_wo);
    cudaGetSymbolAddress((void**)&vt, g_vt);

    static bool attr_set = false;
    if (!attr_set) {
        cudaFuncSetAttribute(attn_f16_kernel,
                             cudaFuncAttributeMaxDynamicSharedMemorySize, SMEM_ATTN);
        cudaFuncSetAttribute(gemm_f16<0>,
                             cudaFuncAttributeMaxDynamicSharedMemorySize, SMEM_GEMM);
        cudaFuncSetAttribute(gemm_f16<1>,
                             cudaFuncAttributeMaxDynamicSharedMemorySize, SMEM_GEMM);
        attr_set = true;
    }

    const int M = BB * LL;   // 8192
    const int Kw = DD / 2;   // 512 words

    // prepass: fp32 -> fp16 words, pos8 word-perm (same perm on both operands)
    {
        int ng = (M * DD) / 16;
        perm_f16_kernel<<<(ng + 255) / 256, 256>>>(x, xt, M, DD);
        ng = (3 * DD * DD) / 16;
        perm_f16_kernel<<<(ng + 255) / 256, 256>>>(Wqkv, wq, 3 * DD, DD);
        ng = (DD * DD) / 16;
        perm_f16_kernel<<<(ng + 255) / 256, 256>>>(Wout, wo, DD, DD);
    }

    // 1) QKV projection (fp16 words out; Q scaled; Q,K word-perm'd, V linear)
    {
        dim3 grid((3 * DD) / 128, M / 128);
        gemm_f16<1><<<grid, 128, SMEM_GEMM>>>(xt, wq, bqkv, qkv, M, 3 * DD, Kw);
    }

    // 1b) V transpose -> [(b,h,hd)][seq-pairs]
    {
        dim3 grid(BB * HH, LL / 64);
        transpose_v_kernel<<<grid, 128>>>(qkv, vt);
    }

    // 2) causal attention
    {
        dim3 grid(LL / 128, HH, BB);
        attn_f16_kernel<<<grid, 128, SMEM_ATTN>>>(qkv, vt, att);
    }

    // 3) output projection (fp32 out)
    {
        dim3 grid(DD / 128, M / 128);
        gemm_f16<0><<<grid, 128, SMEM_GEMM>>>((const uint32_t*)att, wo, bout, outp,
                                              M, DD, Kw);
    }
}

// round 9
// speedup vs baseline: 1.8566x; 1.0227x over previous
#include <cuda_runtime.h>
#include <math.h>
#include <stdint.h>

#define BB 4
#define LL 2048
#define DD 1024
#define HH 16
#define HD 64

// Q prescale: 1/sqrt(64) * log2(e) -> softmax in exp2 domain.
#define QSCALE 0.1803368801111204f

// Scratch (device globals). All fp16 payloads stored as packed uint32 words.
__device__ float    g_qkv[(size_t)BB * LL * 3 * DD];       // fp16 words [M][1536]
__device__ float    g_att[(size_t)BB * LL * DD];           // fp16 words [M][512]
__device__ uint32_t g_xt  [(size_t)BB * LL * DD];          // x fp16 words [M][512]
__device__ uint32_t g_wq  [(size_t)3 * DD * DD];           // Wqkv fp16 words [3072][512]
__device__ uint32_t g_wo  [(size_t)DD * DD];               // Wout fp16 words [1024][512]
__device__ uint32_t g_vt  [(size_t)BB * HH * HD * (LL/2)]; // V^T fp16 words [(b,h,hd)][1024]

// pos8 on word index within an 8-word (16-elem) group: i<4 -> 2i, else 2i-7.
__device__ __host__ __forceinline__ int pos8(int i) {
    return (i < 4) ? (i << 1) : ((i << 1) - 7);
}

__device__ __forceinline__ uint32_t pack_f16x2(float lo, float hi) {
    uint32_t r;
    asm("cvt.rn.f16x2.f32 %0, %1, %2;" : "=r"(r) : "f"(hi), "f"(lo));
    return r;
}

__device__ __forceinline__ void cp_async16(uint32_t smem_addr, const void* gptr) {
    asm volatile("cp.async.cg.shared.global [%0], [%1], 16;\n"
                 :: "r"(smem_addr), "l"(gptr));
}
__device__ __forceinline__ void cp_commit() {
    asm volatile("cp.async.commit_group;\n" ::: "memory");
}
template <int N>
__device__ __forceinline__ void cp_wait() {
    asm volatile("cp.async.wait_group %0;\n" :: "n"(N) : "memory");
}

// m16n8k16 f16 mma, f32 acc.
__device__ __forceinline__ void mma_f16(float* d, const uint32_t* a,
                                        uint32_t b0, uint32_t b1) {
    asm volatile(
        "mma.sync.aligned.m16n8k16.row.col.f32.f16.f16.f32 "
        "{%0,%1,%2,%3}, {%4,%5,%6,%7}, {%8,%9}, {%0,%1,%2,%3};\n"
        : "+f"(d[0]), "+f"(d[1]), "+f"(d[2]), "+f"(d[3])
        : "r"(a[0]), "r"(a[1]), "r"(a[2]), "r"(a[3]), "r"(b0), "r"(b1));
}

// ---------------------------------------------------------------------------
// Prepass: fp32 -> fp16 words, word index pos8-permuted within 16-elem groups.
// ---------------------------------------------------------------------------
__global__ void perm_f16_kernel(const float* __restrict__ in,
                                uint32_t* __restrict__ out, int rows, int cols) {
    int gid = blockIdx.x * blockDim.x + threadIdx.x;
    const int gpr = cols >> 4;
    if (gid >= rows * gpr) return;
    const int r = gid / gpr;
    const int gk = gid - r * gpr;
    const float* ip = in + (size_t)r * cols + gk * 16;
    uint32_t* op = out + (size_t)r * (cols >> 1) + gk * 8;
    float e[16];
#pragma unroll
    for (int i = 0; i < 16; i += 4) {
        float4 v = *(const float4*)(ip + i);
        e[i] = v.x; e[i + 1] = v.y; e[i + 2] = v.z; e[i + 3] = v.w;
    }
#pragma unroll
    for (int i = 0; i < 8; i++)
        op[pos8(i)] = pack_f16x2(e[2 * i], e[2 * i + 1]);
}

// ---------------------------------------------------------------------------
// fp16 GEMM (mma.sync m16n8k16), C = A @ W^T + bias.
// Block 128x128, kTile 32 words (64 elems), 4 warps (2x2), warp 64x64.
// 3-stage cp.async; XOR-swizzled 32-word rows (padding-free, conflict-free);
// register double-buffered fragments (LDS for step s+1 hidden under MMAs of s).
// MODE 0: fp32 out + bias. MODE 1: fp16 words out, Q cols scaled, Q/K word-perm.
// ---------------------------------------------------------------------------
#define GBUF (128 * 32)                 // words per operand per stage
#define SMEM_GEMM (3 * GBUF * 2 * 4)    // 96 KB

__device__ __forceinline__ uint32_t swz32(uint32_t row, uint32_t w) {
    return row * 32 + (w ^ ((row & 3) << 3));
}

template <int MODE>
__global__ __launch_bounds__(128) void gemm_f16(
    const uint32_t* __restrict__ A, const uint32_t* __restrict__ W,
    const float* __restrict__ bias, float* __restrict__ C,
    int M, int N, int Kw)
{
    extern __shared__ uint32_t gsm[];   // As[3][GBUF] | Ws[3][GBUF]

    const int tid = threadIdx.x;
    const int lane = tid & 31;
    const int ww = tid >> 5;
    const int wr = ww >> 1;
    const int wc = ww & 1;
    const int qr = lane >> 2;
    const int qc = lane & 3;
    const int bm = blockIdx.y * 128;
    const int bn = blockIdx.x * 128;

    float acc[4][8][4];
#pragma unroll
    for (int i = 0; i < 4; i++)
#pragma unroll
        for (int j = 0; j < 8; j++)
#pragma unroll
            for (int c = 0; c < 4; c++) acc[i][j][c] = 0.0f;

    const uint32_t sm_base = (uint32_t)__cvta_generic_to_shared(gsm);
    const int nkt = Kw / 32;

    auto stage = [&](int kt_idx, int s) {
#pragma unroll
        for (int i = 0; i < 8; i++) {       // A: 1024 chunks of 16B
            const int q = i * 128 + tid;
            const int r = q >> 3, c = q & 7;
            cp_async16(sm_base + (uint32_t)((s * GBUF + swz32(r, c * 4)) * 4),
                       A + (size_t)(bm + r) * Kw + kt_idx * 32 + c * 4);
        }
#pragma unroll
        for (int i = 0; i < 8; i++) {       // W: 1024 chunks
            const int q = i * 128 + tid;
            const int r = q >> 3, c = q & 7;
            cp_async16(sm_base + (uint32_t)((3 * GBUF + s * GBUF + swz32(r, c * 4)) * 4),
                       W + (size_t)(bn + r) * Kw + kt_idx * 32 + c * 4);
        }
        cp_commit();
    };

    stage(0, 0);
    stage(1, 1);

    int s = 0;
    for (int kt = 0; kt < nkt; kt++) {
        if (kt + 1 < nkt) cp_wait<1>();
        else              cp_wait<0>();
        __syncthreads();
        if (kt + 2 < nkt) {
            int s2 = s + 2; if (s2 >= 3) s2 -= 3;
            stage(kt + 2, s2);
        }

        const uint32_t* As = gsm + s * GBUF;
        const uint32_t* Ws = gsm + 3 * GBUF + s * GBUF;

        // register double-buffered fragments over 4 k16-steps
        uint32_t aa[2][4][4], bb[2][8][2];

#define LDFRAG(buf, ks)                                                        \
        do {                                                                   \
            _Pragma("unroll")                                                  \
            for (int mi = 0; mi < 4; mi++) {                                   \
                const int mrow = wr * 64 + mi * 16 + qr;                       \
                const uint2 u0 = *(const uint2*)&As[swz32(mrow, (ks) + 2 * qc)];      \
                const uint2 u1 = *(const uint2*)&As[swz32(mrow + 8, (ks) + 2 * qc)];  \
                aa[buf][mi][0] = u0.x; aa[buf][mi][1] = u1.x;                  \
                aa[buf][mi][2] = u0.y; aa[buf][mi][3] = u1.y;                  \
            }                                                                  \
            _Pragma("unroll")                                                  \
            for (int ni = 0; ni < 8; ni++) {                                   \
                const int nrow = wc * 64 + ni * 8 + qr;                        \
                const uint2 v = *(const uint2*)&Ws[swz32(nrow, (ks) + 2 * qc)];       \
                bb[buf][ni][0] = v.x; bb[buf][ni][1] = v.y;                    \
            }                                                                  \
        } while (0)

        LDFRAG(0, 0);
#pragma unroll
        for (int st = 0; st < 4; st++) {
            const int cur = st & 1;
            if (st < 3) {
                const int nxt = (st + 1) & 1;
                switch (st) {
                    case 0: LDFRAG(nxt, 8);  break;
                    case 1: LDFRAG(nxt, 16); break;
                    default: LDFRAG(nxt, 24); break;
                }
            }
#pragma unroll
            for (int mi = 0; mi < 4; mi++)
#pragma unroll
                for (int ni = 0; ni < 8; ni++)
                    mma_f16(acc[mi][ni], aa[cur][mi], bb[cur][ni][0], bb[cur][ni][1]);
        }
#undef LDFRAG

        s++; if (s == 3) s = 0;
    }

#pragma unroll
    for (int mi = 0; mi < 4; mi++) {
        const int row = bm + wr * 64 + mi * 16 + qr;
#pragma unroll
        for (int ni = 0; ni < 8; ni++) {
            const int col = bn + wc * 64 + ni * 8 + qc * 2;
            const float b0 = bias[col], b1 = bias[col + 1];
            float* d = acc[mi][ni];
            float v00 = d[0] + b0, v01 = d[1] + b1;
            float v10 = d[2] + b0, v11 = d[3] + b1;
            if (MODE == 1) {
                const float sc = (col < DD) ? QSCALE : 1.0f;
                v00 *= sc; v01 *= sc; v10 *= sc; v11 *= sc;
                const int w = col >> 1;
                const int wp = (col < 2 * DD) ? ((w & ~7) | pos8(w & 7)) : w;
                uint32_t* C32 = (uint32_t*)C;
                C32[(size_t)row * (N >> 1) + wp]       = pack_f16x2(v00, v01);
                C32[(size_t)(row + 8) * (N >> 1) + wp] = pack_f16x2(v10, v11);
            } else {
                *(float2*)(C + (size_t)row * N + col)       = make_float2(v00, v01);
                *(float2*)(C + (size_t)(row + 8) * N + col) = make_float2(v10, v11);
            }
        }
    }
}

// ---------------------------------------------------------------------------
// V transpose: qkv V section -> g_vt [(b,h,hd)][seq-pairs], seq-words pos8'd.
// ---------------------------------------------------------------------------
__global__ __launch_bounds__(128) void transpose_v_kernel(
    const float* __restrict__ qkvf, uint32_t* __restrict__ vt)
{
    __shared__ uint32_t ts[64][33];
    const int bh = blockIdx.x;
    const int b = bh >> 4, h = bh & 15;
    const int sc = blockIdx.y;
    const int tid = threadIdx.x;

    const uint32_t* vg = (const uint32_t*)qkvf
        + ((size_t)(b * LL + sc * 64)) * 1536 + 1024 + h * 32;
#pragma unroll
    for (int i = 0; i < 16; i++) {
        const int q = i * 128 + tid;
        const int r = q >> 5, c = q & 31;
        ts[r][c] = vg[(size_t)r * 1536 + c];
    }
    __syncthreads();

#pragma unroll
    for (int i = 0; i < 16; i++) {
        const int q = i * 128 + tid;
        const int hd = q >> 5, sw = q & 31;
        const uint32_t w0 = ts[2 * sw][hd >> 1];
        const uint32_t w1 = ts[2 * sw + 1][hd >> 1];
        const uint32_t sh = (hd & 1) * 16;
        const uint32_t val = ((w0 >> sh) & 0xffffu) | (((w1 >> sh) & 0xffffu) << 16);
        const int swp = (sw & ~7) | pos8(sw & 7);
        vt[((size_t)(bh * 64 + hd)) * (LL / 2) + sc * 32 + swp] = val;
    }
}

// ---------------------------------------------------------------------------
// Causal flash attention, fp16 mma (unchanged from R8, passing).
// ---------------------------------------------------------------------------
#define AST 40
#define TILE_WORDS (64 * AST)
#define OFF_K0 0
#define OFF_V0 (2 * TILE_WORDS)
#define SMEM_ATTN (4 * TILE_WORDS * 4)   // 40 KB

__global__ __launch_bounds__(128) void attn_f16_kernel(
    const float* __restrict__ qkvf, const uint32_t* __restrict__ vt,
    float* __restrict__ outf)
{
    extern __shared__ uint32_t sm[];
    const uint32_t* qkv = (const uint32_t*)qkvf;
    uint32_t* att = (uint32_t*)outf;

    const int qt = gridDim.x - 1 - blockIdx.x;
    const int h  = blockIdx.y;
    const int b  = blockIdx.z;

    const int tid = threadIdx.x;
    const int lane = tid & 31;
    const int wid = tid >> 5;
    const int qr = lane >> 2;
    const int qc = lane & 3;

    const uint32_t sm_base = (uint32_t)__cvta_generic_to_shared(sm);

    uint32_t qa[2][4][4];
    const uint32_t* qb = qkv + ((size_t)(b * LL + qt * 128 + wid * 32)) * 1536 + h * 32;
#pragma unroll
    for (int mi = 0; mi < 2; mi++)
#pragma unroll
        for (int ks = 0; ks < 4; ks++) {
            const size_t r0 = (size_t)(mi * 16 + qr) * 1536;
            const uint2 u0 = *(const uint2*)(qb + r0 + ks * 8 + 2 * qc);
            const uint2 u1 = *(const uint2*)(qb + r0 + 8 * 1536 + ks * 8 + 2 * qc);
            qa[mi][ks][0] = u0.x; qa[mi][ks][1] = u1.x;
            qa[mi][ks][2] = u0.y; qa[mi][ks][3] = u1.y;
        }

    float o[2][8][4];
    float m[2][2], l[2][2];
#pragma unroll
    for (int mi = 0; mi < 2; mi++) {
        m[mi][0] = m[mi][1] = -INFINITY;
        l[mi][0] = l[mi][1] = 0.0f;
#pragma unroll
        for (int j = 0; j < 8; j++)
#pragma unroll
            for (int c = 0; c < 4; c++) o[mi][j][c] = 0.0f;
    }

    const int jmax = 2 * qt + 1;
    const uint32_t* vtb = vt + ((size_t)((b * HH + h) * 64)) * (LL / 2);

    auto stage = [&](int jt, int s) {
        const uint32_t* kg = qkv + ((size_t)(b * LL + jt * 64)) * 1536 + 512 + h * 32;
#pragma unroll
        for (int i = 0; i < 4; i++) {
            const int q = i * 128 + tid;
            const int r = q >> 3, c = q & 7;
            cp_async16(sm_base + (uint32_t)((OFF_K0 + s * TILE_WORDS + r * AST + c * 4) * 4),
                       kg + (size_t)r * 1536 + c * 4);
        }
#pragma unroll
        for (int i = 0; i < 4; i++) {
            const int q = i * 128 + tid;
            const int r = q >> 3, c = q & 7;
            cp_async16(sm_base + (uint32_t)((OFF_V0 + s * TILE_WORDS + r * AST + c * 4) * 4),
                       vtb + (size_t)r * (LL / 2) + jt * 32 + c * 4);
        }
        cp_commit();
    };

    stage(0, 0);

    for (int jt = 0; jt <= jmax; jt++) {
        const int s = jt & 1;
        __syncthreads();
        if (jt + 1 <= jmax) { stage(jt + 1, s ^ 1); cp_wait<1>(); }
        else                { cp_wait<0>(); }
        __syncthreads();

        const uint32_t* Ks = sm + OFF_K0 + s * TILE_WORDS;
        const uint32_t* Vs = sm + OFF_V0 + s * TILE_WORDS;

        const int wrow_min = qt * 128 + wid * 32;
        const bool tile_dead = (jt * 64) > (wrow_min + 31);

        if (!tile_dead) {
            float sreg[2][8][4];
#pragma unroll
            for (int mi = 0; mi < 2; mi++)
#pragma unroll
                for (int j = 0; j < 8; j++)
#pragma unroll
                    for (int c = 0; c < 4; c++) sreg[mi][j][c] = 0.0f;

#pragma unroll
            for (int ks = 0; ks < 4; ks++) {
#pragma unroll
                for (int j = 0; j < 8; j++) {
                    const uint2 kk = *(const uint2*)&Ks[(j * 8 + qr) * AST + ks * 8 + 2 * qc];
                    mma_f16(sreg[0][j], qa[0][ks], kk.x, kk.y);
                    mma_f16(sreg[1][j], qa[1][ks], kk.x, kk.y);
                }
            }

            if ((jt + 1) * 64 - 1 > wrow_min) {
#pragma unroll
                for (int mi = 0; mi < 2; mi++) {
                    const int r0 = wrow_min + mi * 16 + qr;
#pragma unroll
                    for (int j = 0; j < 8; j++) {
                        const int c0 = jt * 64 + j * 8 + qc * 2;
                        if (c0     > r0)     sreg[mi][j][0] = -INFINITY;
                        if (c0 + 1 > r0)     sreg[mi][j][1] = -INFINITY;
                        if (c0     > r0 + 8) sreg[mi][j][2] = -INFINITY;
                        if (c0 + 1 > r0 + 8) sreg[mi][j][3] = -INFINITY;
                    }
                }
            }

#pragma unroll
            for (int mi = 0; mi < 2; mi++) {
                float mt0 = -INFINITY, mt1 = -INFINITY;
#pragma unroll
                for (int j = 0; j < 8; j++) {
                    mt0 = fmaxf(mt0, fmaxf(sreg[mi][j][0], sreg[mi][j][1]));
                    mt1 = fmaxf(mt1, fmaxf(sreg[mi][j][2], sreg[mi][j][3]));
                }
#pragma unroll
                for (int off = 1; off <= 2; off <<= 1) {
                    mt0 = fmaxf(mt0, __shfl_xor_sync(0xffffffffu, mt0, off));
                    mt1 = fmaxf(mt1, __shfl_xor_sync(0xffffffffu, mt1, off));
                }
                const float mn0 = fmaxf(m[mi][0], mt0);
                const float mn1 = fmaxf(m[mi][1], mt1);
                const float al0 = exp2f(m[mi][0] - mn0);
                const float al1 = exp2f(m[mi][1] - mn1);
                m[mi][0] = mn0; m[mi][1] = mn1;
                float rs0 = 0.0f, rs1 = 0.0f;
#pragma unroll
                for (int j = 0; j < 8; j++) {
                    sreg[mi][j][0] = exp2f(sreg[mi][j][0] - mn0);
                    sreg[mi][j][1] = exp2f(sreg[mi][j][1] - mn0);
                    sreg[mi][j][2] = exp2f(sreg[mi][j][2] - mn1);
                    sreg[mi][j][3] = exp2f(sreg[mi][j][3] - mn1);
                    rs0 += sreg[mi][j][0] + sreg[mi][j][1];
                    rs1 += sreg[mi][j][2] + sreg[mi][j][3];
                }
#pragma unroll
                for (int off = 1; off <= 2; off <<= 1) {
                    rs0 += __shfl_xor_sync(0xffffffffu, rs0, off);
                    rs1 += __shfl_xor_sync(0xffffffffu, rs1, off);
                }
                l[mi][0] = l[mi][0] * al0 + rs0;
                l[mi][1] = l[mi][1] * al1 + rs1;
#pragma unroll
                for (int j = 0; j < 8; j++) {
                    o[mi][j][0] *= al0; o[mi][j][1] *= al0;
                    o[mi][j][2] *= al1; o[mi][j][3] *= al1;
                }
            }

#pragma unroll
            for (int ks = 0; ks < 4; ks++) {
                uint32_t pa0[4], pa1[4];
                pa0[0] = pack_f16x2(sreg[0][2 * ks][0],     sreg[0][2 * ks][1]);
                pa0[1] = pack_f16x2(sreg[0][2 * ks][2],     sreg[0][2 * ks][3]);
                pa0[2] = pack_f16x2(sreg[0][2 * ks + 1][0], sreg[0][2 * ks + 1][1]);
                pa0[3] = pack_f16x2(sreg[0][2 * ks + 1][2], sreg[0][2 * ks + 1][3]);
                pa1[0] = pack_f16x2(sreg[1][2 * ks][0],     sreg[1][2 * ks][1]);
                pa1[1] = pack_f16x2(sreg[1][2 * ks][2],     sreg[1][2 * ks][3]);
                pa1[2] = pack_f16x2(sreg[1][2 * ks + 1][0], sreg[1][2 * ks + 1][1]);
                pa1[3] = pack_f16x2(sreg[1][2 * ks + 1][2], sreg[1][2 * ks + 1][3]);
#pragma unroll
                for (int j = 0; j < 8; j++) {
                    const uint2 vv = *(const uint2*)&Vs[(j * 8 + qr) * AST + ks * 8 + 2 * qc];
                    mma_f16(o[0][j], pa0, vv.x, vv.y);
                    mma_f16(o[1][j], pa1, vv.x, vv.y);
                }
            }
        }
    }

    const int orow0 = b * LL + qt * 128 + wid * 32;
#pragma unroll
    for (int mi = 0; mi < 2; mi++) {
        const float inv0 = 1.0f / l[mi][0];
        const float inv1 = 1.0f / l[mi][1];
        const size_t r0 = (size_t)(orow0 + mi * 16 + qr) * 512;
#pragma unroll
        for (int j = 0; j < 8; j++) {
            const int wl = j * 4 + qc;
            const int wp = h * 32 + ((wl & ~7) | pos8(wl & 7));
            att[r0 + wp]             = pack_f16x2(o[mi][j][0] * inv0, o[mi][j][1] * inv0);
            att[r0 + 8 * 512 + wp]   = pack_f16x2(o[mi][j][2] * inv1, o[mi][j][3] * inv1);
        }
    }
}

// ---------------------------------------------------------------------------
extern "C" void kernel_launch(void* const* d_in, const int* in_sizes, int n_in,
                              void* d_out, int out_size)
{
    const float* x    = (const float*)d_in[0];
    const float* Wqkv = (const float*)d_in[1];
    const float* bqkv = (const float*)d_in[2];
    const float* Wout = (const float*)d_in[3];
    const float* bout = (const float*)d_in[4];
    float* outp = (float*)d_out;

    float *qkv = nullptr, *att = nullptr;
    uint32_t *xt = nullptr, *wq = nullptr, *wo = nullptr, *vt = nullptr;
    cudaGetSymbolAddress((void**)&qkv, g_qkv);
    cudaGetSymbolAddress((void**)&att, g_att);
    cudaGetSymbolAddress((void**)&xt, g_xt);
    cudaGetSymbolAddress((void**)&wq, g_wq);
    cudaGetSymbolAddress((void**)&wo, g_wo);
    cudaGetSymbolAddress((void**)&vt, g_vt);

    static bool attr_set = false;
    if (!attr_set) {
        cudaFuncSetAttribute(attn_f16_kernel,
                             cudaFuncAttributeMaxDynamicSharedMemorySize, SMEM_ATTN);
        cudaFuncSetAttribute(gemm_f16<0>,
                             cudaFuncAttributeMaxDynamicSharedMemorySize, SMEM_GEMM);
        cudaFuncSetAttribute(gemm_f16<1>,
                             cudaFuncAttributeMaxDynamicSharedMemorySize, SMEM_GEMM);
        attr_set = true;
    }

    const int M = BB * LL;   // 8192
    const int Kw = DD / 2;   // 512 words

    // prepass: fp32 -> fp16 words, pos8 word-perm (same perm on both operands)
    {
        int ng = (M * DD) / 16;
        perm_f16_kernel<<<(ng + 255) / 256, 256>>>(x, xt, M, DD);
        ng = (3 * DD * DD) / 16;
        perm_f16_kernel<<<(ng + 255) / 256, 256>>>(Wqkv, wq, 3 * DD, DD);
        ng = (DD * DD) / 16;
        perm_f16_kernel<<<(ng + 255) / 256, 256>>>(Wout, wo, DD, DD);
    }

    // 1) QKV projection (fp16 words out; Q scaled; Q,K word-perm'd, V linear)
    {
        dim3 grid((3 * DD) / 128, M / 128);
        gemm_f16<1><<<grid, 128, SMEM_GEMM>>>(xt, wq, bqkv, qkv, M, 3 * DD, Kw);
    }

    // 1b) V transpose -> [(b,h,hd)][seq-pairs]
    {
        dim3 grid(BB * HH, LL / 64);
        transpose_v_kernel<<<grid, 128>>>(qkv, vt);
    }

    // 2) causal attention
    {
        dim3 grid(LL / 128, HH, BB);
        attn_f16_kernel<<<grid, 128, SMEM_ATTN>>>(qkv, vt, att);
    }

    // 3) output projection (fp32 out)
    {
        dim3 grid(DD / 128, M / 128);
        gemm_f16<0><<<grid, 128, SMEM_GEMM>>>((const uint32_t*)att, wo, bout, outp,
                                              M, DD, Kw);
    }
}